// round 4
// baseline (speedup 1.0000x reference)
#include <cuda_runtime.h>
#include <cstdint>

#define BB 2
#define SS 2048
#define DD 1024
#define HH 16
#define HDD 64

// ---------------- scratch (allocation-free: __device__ globals) ----------------
__device__ float g_q[BB * SS * HH * HDD];      // 16 MB
__device__ float g_k[BB * SS * HH * HDD];      // 16 MB
__device__ float g_v[BB * SS * HH * HDD];      // 16 MB
__device__ float g_ctx[BB * SS * HH * HDD];    // 16 MB
__device__ float g_bias[HH * SS * SS];         // 256 MB

// ---------------- generic fp32 GEMM: C[M,N] = A[M,K] * B[K,N] + bias[N] --------
// BM=128, BN=64, BK=16, 256 threads, 8x4 per-thread microtile
#define BM 128
#define BN 64
#define BK 16

__global__ void __launch_bounds__(256)
gemm_bias_kernel(const float* __restrict__ A, const float* __restrict__ Bm,
                 const float* __restrict__ bias, float* __restrict__ C,
                 int M, int N, int K)
{
    __shared__ float AsT[BK][BM + 4];   // [k][m]
    __shared__ float Bs[BK][BN];        // [k][n]

    const int tid = threadIdx.x;
    const int tx = tid & 15;            // n group (4 cols)
    const int ty = tid >> 4;            // m group (8 rows)
    const int m0 = blockIdx.y * BM;
    const int n0 = blockIdx.x * BN;

    float acc[8][4];
#pragma unroll
    for (int i = 0; i < 8; ++i)
#pragma unroll
        for (int j = 0; j < 4; ++j) acc[i][j] = 0.f;

    for (int k0 = 0; k0 < K; k0 += BK) {
        // load A tile (128 x 16) as float4, store transposed
#pragma unroll
        for (int it = 0; it < 2; ++it) {
            int idx = tid + it * 256;          // 512 float4s
            int r   = idx >> 2;                // 0..127
            int kk  = (idx & 3) * 4;
            float4 v = *(const float4*)(A + (size_t)(m0 + r) * K + k0 + kk);
            AsT[kk + 0][r] = v.x;
            AsT[kk + 1][r] = v.y;
            AsT[kk + 2][r] = v.z;
            AsT[kk + 3][r] = v.w;
        }
        // load B tile (16 x 64)
        {
            int r  = tid >> 4;                 // 0..15
            int c4 = (tid & 15) * 4;
            *(float4*)&Bs[r][c4] = *(const float4*)(Bm + (size_t)(k0 + r) * N + n0 + c4);
        }
        __syncthreads();

#pragma unroll
        for (int kk = 0; kk < BK; ++kk) {
            float4 a0 = *(float4*)&AsT[kk][ty * 8];
            float4 a1 = *(float4*)&AsT[kk][ty * 8 + 4];
            float4 b4 = *(float4*)&Bs[kk][tx * 4];
            float av[8] = {a0.x, a0.y, a0.z, a0.w, a1.x, a1.y, a1.z, a1.w};
            float bv[4] = {b4.x, b4.y, b4.z, b4.w};
#pragma unroll
            for (int i = 0; i < 8; ++i)
#pragma unroll
                for (int j = 0; j < 4; ++j) acc[i][j] += av[i] * bv[j];
        }
        __syncthreads();
    }

    float4 bb = *(const float4*)(bias + n0 + tx * 4);
#pragma unroll
    for (int i = 0; i < 8; ++i) {
        float4 o;
        o.x = acc[i][0] + bb.x;
        o.y = acc[i][1] + bb.y;
        o.z = acc[i][2] + bb.z;
        o.w = acc[i][3] + bb.w;
        *(float4*)(C + (size_t)(m0 + ty * 8 + i) * N + n0 + tx * 4) = o;
    }
}

// ---------------- relative-position bias: bias[h][q][k] = sum_c rel[c][h]*Qb[q][k][c]
__global__ void __launch_bounds__(256)
bias_kernel(const float* __restrict__ Qb, const float* __restrict__ rel,
            float* __restrict__ bias)
{
    __shared__ float srel[128];  // [c*16 + h]
    if (threadIdx.x < 128) srel[threadIdx.x] = rel[threadIdx.x];
    __syncthreads();

    size_t p = (size_t)blockIdx.x * blockDim.x + threadIdx.x;  // 0 .. S*S-1
    float qb[8];
    *(float4*)qb       = *(const float4*)(Qb + p * 8);
    *(float4*)(qb + 4) = *(const float4*)(Qb + p * 8 + 4);

#pragma unroll
    for (int h = 0; h < 16; ++h) {
        float a = 0.f;
#pragma unroll
        for (int c = 0; c < 8; ++c) a += srel[c * 16 + h] * qb[c];
        bias[(size_t)h * SS * SS + p] = a;
    }
}

// ---------------- LayerNorm over HD=64 for q and k (one warp per vector) -------
__global__ void __launch_bounds__(256)
qk_ln_kernel(float* __restrict__ q, float* __restrict__ k,
             const float* __restrict__ qs, const float* __restrict__ ks)
{
    int gwarp = (blockIdx.x * blockDim.x + threadIdx.x) >> 5;
    int lane = threadIdx.x & 31;
    // 65536 vectors per tensor (B*S*H), 2 tensors
    int tensor = gwarp >> 16;
    int vec = gwarp & 65535;
    float* base = (tensor == 0 ? q : k) + (size_t)vec * 64;
    const float* sc = (tensor == 0 ? qs : ks);

    float2 v = *(float2*)(base + lane * 2);
    float s = v.x + v.y;
    float s2 = v.x * v.x + v.y * v.y;
#pragma unroll
    for (int d = 16; d > 0; d >>= 1) {
        s  += __shfl_xor_sync(0xffffffffu, s, d);
        s2 += __shfl_xor_sync(0xffffffffu, s2, d);
    }
    float mu = s * (1.f / 64.f);
    float var = s2 * (1.f / 64.f) - mu * mu;
    float r = rsqrtf(var + 1e-6f);
    float2 o;
    o.x = (v.x - mu) * r * sc[lane * 2];
    o.y = (v.y - mu) * r * sc[lane * 2 + 1];
    *(float2*)(base + lane * 2) = o;
}

// ---------------- flash attention: CTA = (q_tile=64, h, b), 64-wide K tiles ----
__global__ void __launch_bounds__(256)
attn_kernel(const float* __restrict__ gq, const float* __restrict__ gk,
            const float* __restrict__ gv, const float* __restrict__ bias,
            float* __restrict__ gctx)
{
    extern __shared__ float smem_f[];
    float (*sQT)[68] = (float(*)[68])(smem_f);                 // [hd][q]
    float (*sKT)[68] = (float(*)[68])(smem_f + 64 * 68);       // [hd][k]
    float (*sV)[68]  = (float(*)[68])(smem_f + 2 * 64 * 68);   // [k][hd]
    float (*sP)[68]  = (float(*)[68])(smem_f + 3 * 64 * 68);   // [q][k]

    const int tid = threadIdx.x;
    const int tx = tid & 15;     // 4-wide col group (k or hd)
    const int ty = tid >> 4;     // 4-wide row group (q)
    const int q0 = blockIdx.x * 64;
    const int h  = blockIdx.y;
    const int b  = blockIdx.z;
    const float scale = 0.125f;  // 1/sqrt(64)

    // load Q tile transposed, pre-scaled
#pragma unroll
    for (int it = 0; it < 4; ++it) {
        int idx = tid + it * 256;          // 1024 float4s
        int r  = idx >> 4;                 // q row
        int c4 = (idx & 15) * 4;           // hd
        size_t goff = ((((size_t)b * SS + q0 + r) * HH + h) << 6) + c4;
        float4 v = *(const float4*)(gq + goff);
        sQT[c4 + 0][r] = v.x * scale;
        sQT[c4 + 1][r] = v.y * scale;
        sQT[c4 + 2][r] = v.z * scale;
        sQT[c4 + 3][r] = v.w * scale;
    }

    float m_i[4], l_i[4], o[4][4];
#pragma unroll
    for (int i = 0; i < 4; ++i) {
        m_i[i] = -1e30f;
        l_i[i] = 0.f;
#pragma unroll
        for (int j = 0; j < 4; ++j) o[i][j] = 0.f;
    }
    __syncthreads();

    for (int k0 = 0; k0 < SS; k0 += 64) {
        // load K tile (transposed) and V tile
#pragma unroll
        for (int it = 0; it < 4; ++it) {
            int idx = tid + it * 256;
            int r  = idx >> 4;             // k row
            int c4 = (idx & 15) * 4;       // hd
            size_t goff = ((((size_t)b * SS + k0 + r) * HH + h) << 6) + c4;
            float4 kv = *(const float4*)(gk + goff);
            sKT[c4 + 0][r] = kv.x;
            sKT[c4 + 1][r] = kv.y;
            sKT[c4 + 2][r] = kv.z;
            sKT[c4 + 3][r] = kv.w;
            *(float4*)&sV[r][c4] = *(const float4*)(gv + goff);
        }
        __syncthreads();

        // scores: init with bias, accumulate (q*scale) . k
        float s[4][4];
#pragma unroll
        for (int i = 0; i < 4; ++i) {
            float4 bb = *(const float4*)(bias + ((size_t)h * SS + q0 + ty * 4 + i) * SS
                                               + k0 + tx * 4);
            s[i][0] = bb.x; s[i][1] = bb.y; s[i][2] = bb.z; s[i][3] = bb.w;
        }
#pragma unroll 8
        for (int hd = 0; hd < 64; ++hd) {
            float4 a4 = *(float4*)&sQT[hd][ty * 4];
            float4 b4 = *(float4*)&sKT[hd][tx * 4];
            float av[4] = {a4.x, a4.y, a4.z, a4.w};
            float bv[4] = {b4.x, b4.y, b4.z, b4.w};
#pragma unroll
            for (int i = 0; i < 4; ++i)
#pragma unroll
                for (int j = 0; j < 4; ++j) s[i][j] += av[i] * bv[j];
        }

        // online softmax (row groups = 16 lanes sharing ty; xor dist < 16 stays in group)
        float tm[4], ps[4];
#pragma unroll
        for (int i = 0; i < 4; ++i)
            tm[i] = fmaxf(fmaxf(s[i][0], s[i][1]), fmaxf(s[i][2], s[i][3]));
#pragma unroll
        for (int d = 1; d < 16; d <<= 1)
#pragma unroll
            for (int i = 0; i < 4; ++i)
                tm[i] = fmaxf(tm[i], __shfl_xor_sync(0xffffffffu, tm[i], d));
#pragma unroll
        for (int i = 0; i < 4; ++i) {
            float mn = fmaxf(m_i[i], tm[i]);
            float alpha = __expf(m_i[i] - mn);
            m_i[i] = mn;
            float p0 = __expf(s[i][0] - mn);
            float p1 = __expf(s[i][1] - mn);
            float p2 = __expf(s[i][2] - mn);
            float p3 = __expf(s[i][3] - mn);
            s[i][0] = p0; s[i][1] = p1; s[i][2] = p2; s[i][3] = p3;
            ps[i] = (p0 + p1) + (p2 + p3);
            l_i[i] *= alpha;
#pragma unroll
            for (int j = 0; j < 4; ++j) o[i][j] *= alpha;
        }
#pragma unroll
        for (int d = 1; d < 16; d <<= 1)
#pragma unroll
            for (int i = 0; i < 4; ++i)
                ps[i] += __shfl_xor_sync(0xffffffffu, ps[i], d);
#pragma unroll
        for (int i = 0; i < 4; ++i) l_i[i] += ps[i];

        // stage P
        __syncthreads();  // everyone done reading sKT / computing scores
#pragma unroll
        for (int i = 0; i < 4; ++i) {
            float4 pv;
            pv.x = s[i][0]; pv.y = s[i][1]; pv.z = s[i][2]; pv.w = s[i][3];
            *(float4*)&sP[ty * 4 + i][tx * 4] = pv;
        }
        __syncthreads();

        // PV: o[q][hd] += P[q][kk] * V[kk][hd]
#pragma unroll 8
        for (int kk = 0; kk < 64; ++kk) {
            float4 v4 = *(float4*)&sV[kk][tx * 4];
            float vv[4] = {v4.x, v4.y, v4.z, v4.w};
            float pv[4];
#pragma unroll
            for (int i = 0; i < 4; ++i) pv[i] = sP[ty * 4 + i][kk];  // broadcast
#pragma unroll
            for (int i = 0; i < 4; ++i)
#pragma unroll
                for (int j = 0; j < 4; ++j) o[i][j] += pv[i] * vv[j];
        }
        __syncthreads();  // before next tile overwrites sKT/sV/sP
    }

    // epilogue: normalize and store ctx
#pragma unroll
    for (int i = 0; i < 4; ++i) {
        float inv = 1.f / l_i[i];
        size_t off = ((((size_t)b * SS + q0 + ty * 4 + i) * HH + h) << 6) + tx * 4;
        float4 ov;
        ov.x = o[i][0] * inv; ov.y = o[i][1] * inv;
        ov.z = o[i][2] * inv; ov.w = o[i][3] * inv;
        *(float4*)(gctx + off) = ov;
    }
}

// ---------------- launcher ------------------------------------------------------
extern "C" void kernel_launch(void* const* d_in, const int* in_sizes, int n_in,
                              void* d_out, int out_size)
{
    (void)in_sizes; (void)n_in; (void)out_size;
    const float* x   = (const float*)d_in[0];
    const float* Qb  = (const float*)d_in[1];
    const float* Wq  = (const float*)d_in[2];
    const float* bq  = (const float*)d_in[3];
    const float* Wk  = (const float*)d_in[4];
    const float* bk  = (const float*)d_in[5];
    const float* Wv  = (const float*)d_in[6];
    const float* bv  = (const float*)d_in[7];
    const float* qs  = (const float*)d_in[8];
    const float* ks  = (const float*)d_in[9];
    const float* rel = (const float*)d_in[10];
    const float* Wo  = (const float*)d_in[11];
    const float* bo  = (const float*)d_in[12];
    float* out = (float*)d_out;

    float *pq, *pk, *pv, *pctx, *pbias;
    cudaGetSymbolAddress((void**)&pq,    g_q);
    cudaGetSymbolAddress((void**)&pk,    g_k);
    cudaGetSymbolAddress((void**)&pv,    g_v);
    cudaGetSymbolAddress((void**)&pctx,  g_ctx);
    cudaGetSymbolAddress((void**)&pbias, g_bias);

    const int M = BB * SS;   // 4096
    const int N = DD;        // 1024
    const int K = DD;        // 1024
    dim3 gg(N / BN, M / BM); // (16, 32)

    // QKV projections
    gemm_bias_kernel<<<gg, 256>>>(x, Wq, bq, pq, M, N, K);
    gemm_bias_kernel<<<gg, 256>>>(x, Wk, bk, pk, M, N, K);
    gemm_bias_kernel<<<gg, 256>>>(x, Wv, bv, pv, M, N, K);

    // relative-position bias (independent of qkv)
    bias_kernel<<<(SS * SS) / 256, 256>>>(Qb, rel, pbias);

    // QK layernorm
    qk_ln_kernel<<<(2 * BB * SS * HH * 32) / 256, 256>>>(pq, pk, qs, ks);

    // attention
    static const int ATTN_SMEM = 4 * 64 * 68 * (int)sizeof(float);  // 69632 B
    cudaFuncSetAttribute(attn_kernel, cudaFuncAttributeMaxDynamicSharedMemorySize,
                         ATTN_SMEM);
    attn_kernel<<<dim3(SS / 64, HH, BB), 256, ATTN_SMEM>>>(pq, pk, pv, pbias, pctx);

    // output projection
    gemm_bias_kernel<<<gg, 256>>>(pctx, Wo, bo, out, M, N, K);
}